// round 13
// baseline (speedup 1.0000x reference)
#include <cuda_runtime.h>
#include <cuda_fp16.h>
#include <cstdint>

typedef unsigned long long ull;

#define CDIM 256
#define KCB  8192
#define NTOK 16384
#define OUT_ELEMS (16*256*32*32)
#define MARGIN 6e-4f

#define KSPL 8                               // codebook splits
#define NCH  (128 / KSPL)                    // 64-code chunks per CTA
#define NTILE 256                            // 64-token tiles
#define VQ_SMEM (32768 + 2*32768)            // tokens(32K) + 2 code stages
#define RR_SMEM (65536 + 32768 + 512)        // codes + 32 tokens + red

__device__ float   g_en[KCB * CDIM];         // normalized codebook fp32
__device__ float   g_corr[KCB];              // 0.5*|e_n|^2
__device__ __half2 g_e2[KCB * 128];          // half2 codebook, [k/64][c2][k%64]
__device__ float   g_zf[NTOK * CDIM];        // normalized tokens fp32 row-major
__device__ __half2 g_z2[NTOK * 128];         // half2 tokens, [n/128][c2][n%128]
__device__ ull     g_topP[KSPL * NTOK];      // per-split packed (score|invidx)
__device__ float   g_top2[KSPL * NTOK];      // per-split second-best
__device__ int     g_idx[NTOK];
__device__ int     g_nflag;
__device__ int     g_list[NTOK];
__device__ ull     g_bestm[NTOK];

// ---------------- helpers ----------------
__device__ __forceinline__ uint32_t smem_u32(const void* p) {
    uint32_t a;
    asm("{ .reg .u64 t; cvta.to.shared.u64 t, %1; cvt.u32.u64 %0, t; }" : "=r"(a) : "l"(p));
    return a;
}
#define CP16(dst, src) asm volatile("cp.async.cg.shared.global [%0], [%1], 16;" :: "r"(dst), "l"(src) : "memory")
#define CP_COMMIT()    asm volatile("cp.async.commit_group;" ::: "memory")
#define CP_WAIT1()     asm volatile("cp.async.wait_group 1;" ::: "memory")
#define CP_WAIT0()     asm volatile("cp.async.wait_group 0;" ::: "memory")

__device__ __forceinline__ unsigned fmap(float v) {
    unsigned u = __float_as_uint(v);
    return (u & 0x80000000u) ? ~u : (u | 0x80000000u);
}
__device__ __forceinline__ float funmap(unsigned u) {
    return __uint_as_float((u & 0x80000000u) ? (u ^ 0x80000000u) : ~u);
}

// ---------------- preprocessing ----------------
__global__ void norm_codebook(const float* __restrict__ emb) {
    if (blockIdx.x == 0 && threadIdx.x == 0) g_nflag = 0;
    int row  = blockIdx.x * 8 + (threadIdx.x >> 5);
    int lane = threadIdx.x & 31;
    const float4* w = (const float4*)(emb + (size_t)row * CDIM);
    float4 a = __ldg(w + lane);
    float4 b = __ldg(w + lane + 32);
    float ss = a.x*a.x + a.y*a.y + a.z*a.z + a.w*a.w
             + b.x*b.x + b.y*b.y + b.z*b.z + b.w*b.w;
    #pragma unroll
    for (int s = 16; s; s >>= 1) ss += __shfl_xor_sync(0xffffffffu, ss, s);
    float inv = 1.0f / fmaxf(sqrtf(ss), 1e-12f);
    float v[8];
    v[0]=a.x*inv; v[1]=a.y*inv; v[2]=a.z*inv; v[3]=a.w*inv;
    v[4]=b.x*inv; v[5]=b.y*inv; v[6]=b.z*inv; v[7]=b.w*inv;
    float4* o = (float4*)(g_en + (size_t)row * CDIM);
    o[lane]      = make_float4(v[0], v[1], v[2], v[3]);
    o[lane + 32] = make_float4(v[4], v[5], v[6], v[7]);
    size_t base = (size_t)(row >> 6) * 8192 + (row & 63);
    g_e2[base + (size_t)(2*lane    ) * 64] = __floats2half2_rn(v[0], v[1]);
    g_e2[base + (size_t)(2*lane + 1) * 64] = __floats2half2_rn(v[2], v[3]);
    g_e2[base + (size_t)(64 + 2*lane    ) * 64] = __floats2half2_rn(v[4], v[5]);
    g_e2[base + (size_t)(64 + 2*lane + 1) * 64] = __floats2half2_rn(v[6], v[7]);
    float ss2 = 0.f;
    #pragma unroll
    for (int j = 0; j < 8; j++) ss2 = fmaf(v[j], v[j], ss2);
    #pragma unroll
    for (int s = 16; s; s >>= 1) ss2 += __shfl_xor_sync(0xffffffffu, ss2, s);
    if (lane == 0) g_corr[row] = 0.5f * ss2;
}

__global__ void __launch_bounds__(256) norm_tokens(const float* __restrict__ z) {
    __shared__ float ssh[2][128];
    int n0 = blockIdx.x * 128;
    int b   = n0 >> 10;
    int hw0 = n0 & 1023;
    int tt = threadIdx.x & 127;
    int p  = threadIdx.x >> 7;
    const float* zp = z + ((size_t)b * CDIM + p * 128) * 1024 + hw0 + tt;

    float ss = 0.f;
    #pragma unroll 8
    for (int c = 0; c < 128; c++) { float v = zp[(size_t)c * 1024]; ss = fmaf(v, v, ss); }
    ssh[p][tt] = ss;
    __syncthreads();
    float inv = 1.0f / fmaxf(sqrtf(ssh[0][tt] + ssh[1][tt]), 1e-12f);

    int n = n0 + tt;
    float* zfout = g_zf + (size_t)n * CDIM + p * 128;
    __half2* z2out = g_z2 + (size_t)blockIdx.x * 16384 + tt;
    #pragma unroll 2
    for (int c = 0; c < 128; c += 8) {
        float v[8];
        #pragma unroll
        for (int j = 0; j < 8; j++) v[j] = zp[(size_t)(c + j) * 1024] * inv;
        *(float4*)(zfout + c)     = make_float4(v[0], v[1], v[2], v[3]);
        *(float4*)(zfout + c + 4) = make_float4(v[4], v[5], v[6], v[7]);
        #pragma unroll
        for (int q = 0; q < 4; q++) {
            int c2 = p * 64 + (c >> 1) + q;
            z2out[(size_t)c2 * 128] = __floats2half2_rn(v[2*q], v[2*q+1]);
        }
    }
}

// ---------------- main: HFMA2 partial GEMM, 64-token tiles, 2 CTA/SM ----------------
__global__ void __launch_bounds__(256, 2) vq_main() {
    extern __shared__ __align__(16) char smem[];
    __half2* tokS = (__half2*)smem;                       // [128 c2][64 tok]
    const uint32_t sa = smem_u32(smem);
    const int tid = threadIdx.x, tc = tid & 15, tg = tid >> 4;
    const int kspl = blockIdx.x >> 8;                     // ksplit-major: wave shares codes
    const int tile = blockIdx.x & 255;
    const int n0 = tile * 64;
    const int gc0 = kspl * NCH;

    {
        const __half2* zsrc = g_z2 + (size_t)(tile >> 1) * 16384 + (tile & 1) * 64;
        #pragma unroll
        for (int j = 0; j < 8; j++) {                     // tokens: 2048 16B units
            int i = tid + j * 256;
            int c2 = i >> 4, q = i & 15;
            CP16(sa + c2*256 + q*16, zsrc + c2*128 + q*4);
        }
        const __half2* e0 = g_e2 + (size_t)gc0 * 8192;
        #pragma unroll
        for (int j = 0; j < 8; j++)  { int i = tid + j*256; CP16(sa + 32768 + i*16, e0 + i*4); }
        CP_COMMIT();
        #pragma unroll
        for (int j = 0; j < 8; j++)  { int i = tid + j*256; CP16(sa + 32768 + 32768 + i*16, e0 + 8192 + i*4); }
        CP_COMMIT();
    }

    float v1[4], v2[4]; int i1[4];
    #pragma unroll
    for (int t = 0; t < 4; t++) { v1[t] = -1e30f; v2[t] = -1e30f; i1[t] = 0; }

    for (int ch = 0; ch < NCH; ch++) {
        if (ch == NCH - 1) CP_WAIT0(); else CP_WAIT1();
        __syncthreads();

        const __half2* codeS = (const __half2*)(smem + 32768 + (ch & 1) * 32768);
        float facc[4][4];
        #pragma unroll
        for (int t = 0; t < 4; t++)
            #pragma unroll
            for (int j = 0; j < 4; j++) facc[t][j] = 0.f;

        #pragma unroll
        for (int seg = 0; seg < 4; seg++) {
            __half2 acc2[2][4][4];                       // parity-split chains
            const __half2 hz = __float2half2_rn(0.f);
            #pragma unroll
            for (int pp = 0; pp < 2; pp++)
                #pragma unroll
                for (int t = 0; t < 4; t++)
                    #pragma unroll
                    for (int j = 0; j < 4; j++) acc2[pp][t][j] = hz;

            #pragma unroll 8
            for (int cs = 0; cs < 32; cs++) {
                int c2 = seg * 32 + cs;
                int pp = cs & 1;
                __half2 zv[4], ev[4];
                *(uint4*)&zv[0] = *(const uint4*)(tokS + c2*64 + tg*4);
                *(uint4*)&ev[0] = *(const uint4*)(codeS + c2*64 + tc*4);
                #pragma unroll
                for (int t = 0; t < 4; t++)
                    #pragma unroll
                    for (int j = 0; j < 4; j++)
                        acc2[pp][t][j] = __hfma2(zv[t], ev[j], acc2[pp][t][j]);
            }
            #pragma unroll
            for (int t = 0; t < 4; t++)
                #pragma unroll
                for (int j = 0; j < 4; j++)
                    facc[t][j] += (__low2float(acc2[0][t][j]) + __high2float(acc2[0][t][j]))
                                + (__low2float(acc2[1][t][j]) + __high2float(acc2[1][t][j]));
        }
        __syncthreads();

        if (ch + 2 < NCH) {
            const __half2* esrc = g_e2 + (size_t)(gc0 + ch + 2) * 8192;
            uint32_t db = sa + 32768 + (ch & 1) * 32768;
            #pragma unroll
            for (int j = 0; j < 8; j++) { int i = tid + j*256; CP16(db + i*16, esrc + i*4); }
        }
        CP_COMMIT();

        int kbase = (gc0 + ch) * 64 + tc * 4;
        #pragma unroll
        for (int t = 0; t < 4; t++)
            #pragma unroll
            for (int j = 0; j < 4; j++) {
                float s = facc[t][j];
                if (s > v1[t]) { v2[t] = v1[t]; v1[t] = s; i1[t] = kbase + j; }
                else if (s > v2[t]) v2[t] = s;
            }
    }

    #pragma unroll
    for (int t = 0; t < 4; t++) {
        ull p = ((ull)fmap(v1[t]) << 13) | (ull)(8191 - i1[t]);
        float s2 = v2[t];
        #pragma unroll
        for (int x = 1; x <= 8; x <<= 1) {
            ull po = __shfl_xor_sync(0xffffffffu, p, x);
            float s2o = __shfl_xor_sync(0xffffffffu, s2, x);
            float va = funmap((unsigned)(p >> 13));
            float vb = funmap((unsigned)(po >> 13));
            s2 = fmaxf(fmaxf(s2, s2o), fminf(va, vb));
            if (po > p) p = po;
        }
        if (tc == 0) {
            int n = n0 + tg * 4 + t;
            g_topP[kspl * NTOK + n] = p;
            g_top2[kspl * NTOK + n] = s2;
        }
    }
}

// ---------------- merge K-split partials, compute margin, build list ----------------
__global__ void merge_tok() {
    int n = blockIdx.x * 256 + threadIdx.x;
    ull best = g_topP[n];
    float v1 = funmap((unsigned)(best >> 13));
    float v2 = g_top2[n];
    #pragma unroll
    for (int s = 1; s < KSPL; s++) {
        ull p = g_topP[s * NTOK + n];
        float w1 = funmap((unsigned)(p >> 13));
        float w2 = g_top2[s * NTOK + n];
        v2 = fmaxf(fmaxf(v2, w2), fminf(v1, w1));
        if (p > best) { best = p; v1 = w1; }
    }
    g_idx[n] = 8191 - (int)(best & 0x1FFF);
    if (v1 - v2 < MARGIN) {
        g_bestm[n] = 0ull;
        int pos = atomicAdd(&g_nflag, 1);
        g_list[pos] = n;
    }
}

// ---------------- rerank: 128 blocks x 64 codes, 32 tokens/iter, 8 tok/thread ----------------
__global__ void __launch_bounds__(256, 1) rerank_part() {
    int cnt = *(volatile int*)&g_nflag;
    if (cnt == 0) return;

    extern __shared__ __align__(16) char rsm[];
    float4* ecv = (float4*)rsm;                 // [64 c4][64 code]
    float4* tzv = (float4*)(rsm + 65536);       // [32 tok][64 c4]
    ull*    red = (ull*)(rsm + 65536 + 32768);  // [32 tok][2 w]

    const int tid = threadIdx.x;
    const int cl  = tid & 63;
    const int g   = tid >> 6;
    const int k0  = blockIdx.x * 64;
    const int k   = k0 + cl;
    const float corr = __ldg(&g_corr[k]);

    {
        const float4* src = (const float4*)(g_en + (size_t)k * CDIM) + g * 16;
        #pragma unroll
        for (int j = 0; j < 16; j++) {
            float4 vv = __ldg(src + j);
            ecv[(g * 16 + j) * 64 + cl] = vv;
        }
    }
    __syncthreads();

    const int witer = (cnt + 31) >> 5;
    for (int it = 0; it < witer; it++) {
        #pragma unroll
        for (int j = 0; j < 8; j++) {
            int i = tid + j * 256;
            int tok = i >> 6, c4 = i & 63;
            int li = it * 32 + tok;
            int n = g_list[(li < cnt) ? li : 0];
            tzv[tok * 64 + c4] = __ldg((const float4*)(g_zf + (size_t)n * CDIM) + c4);
        }
        __syncthreads();

        float s[8];
        #pragma unroll
        for (int t = 0; t < 8; t++) s[t] = 0.f;
        const float4* tz0 = tzv + (g * 8) * 64;
        #pragma unroll 4
        for (int c4 = 0; c4 < 64; c4++) {
            float4 ev = ecv[c4 * 64 + cl];
            #pragma unroll
            for (int t = 0; t < 8; t++) {
                float4 zz = tz0[t * 64 + c4];
                s[t] = fmaf(zz.x, ev.x, s[t]);
                s[t] = fmaf(zz.y, ev.y, s[t]);
                s[t] = fmaf(zz.z, ev.z, s[t]);
                s[t] = fmaf(zz.w, ev.w, s[t]);
            }
        }
        __syncthreads();

        #pragma unroll
        for (int t = 0; t < 8; t++) {
            ull p = ((ull)fmap(s[t] - corr) << 13) | (ull)(8191 - k);
            #pragma unroll
            for (int x = 16; x; x >>= 1) {
                ull o = __shfl_xor_sync(0xffffffffu, p, x);
                if (o > p) p = o;
            }
            if ((tid & 31) == 0) red[(g * 8 + t) * 2 + ((tid >> 5) & 1)] = p;
        }
        __syncthreads();
        if (tid < 32) {
            int li = it * 32 + tid;
            if (li < cnt) {
                ull a = red[tid * 2], b = red[tid * 2 + 1];
                ull p = (b > a) ? b : a;
                atomicMax(&g_bestm[g_list[li]], p);
            }
        }
        __syncthreads();
    }
}

__global__ void rerank_fix() {
    int i = blockIdx.x * 256 + threadIdx.x;
    if (i < *(volatile int*)&g_nflag) {
        int n = g_list[i];
        g_idx[n] = 8191 - (int)(g_bestm[n] & 0x1FFF);
    }
}

// ---------------- output ----------------
__global__ void __launch_bounds__(256) gather_out(float* __restrict__ out) {
    __shared__ float s[32][CDIM + 1];
    __shared__ int sidx[32];
    int n0 = blockIdx.x * 32;
    if (threadIdx.x < 32) sidx[threadIdx.x] = g_idx[n0 + threadIdx.x];
    __syncthreads();
    #pragma unroll 4
    for (int i = 0; i < 32; i++) {
        int lin = threadIdx.x + i * 256;
        int t = lin >> 8, c = lin & 255;
        s[t][c] = g_en[(size_t)sidx[t] * CDIM + c];
    }
    __syncthreads();
    int b   = n0 >> 10;
    int hw0 = n0 & 1023;
    #pragma unroll 4
    for (int i = 0; i < 32; i++) {
        int lin = threadIdx.x + i * 256;
        int c = lin >> 5, t = lin & 31;
        out[((size_t)b * CDIM + c) * 1024 + hw0 + t] = s[t][c];
    }
}

__global__ void idx_out(float* __restrict__ o) {
    int n = blockIdx.x * 256 + threadIdx.x;
    o[n] = (float)g_idx[n];
}

extern "C" void kernel_launch(void* const* d_in, const int* in_sizes, int n_in,
                              void* d_out, int out_size) {
    const float* z   = (const float*)d_in[0];
    const float* emb = (const float*)d_in[1];
    float* out = (float*)d_out;

    cudaFuncSetAttribute(vq_main,     cudaFuncAttributeMaxDynamicSharedMemorySize, VQ_SMEM);
    cudaFuncSetAttribute(rerank_part, cudaFuncAttributeMaxDynamicSharedMemorySize, RR_SMEM);

    norm_codebook<<<KCB / 8, 256>>>(emb);
    norm_tokens<<<NTOK / 128, 256>>>(z);
    vq_main<<<NTILE * KSPL, 256, VQ_SMEM>>>();
    merge_tok<<<NTOK / 256, 256>>>();
    rerank_part<<<128, 256, RR_SMEM>>>();
    rerank_fix<<<NTOK / 256, 256>>>();
    gather_out<<<NTOK / 32, 256>>>(out);
    if (out_size >= OUT_ELEMS + NTOK)
        idx_out<<<NTOK / 256, 256>>>(out + OUT_ELEMS);
}

// round 15
// speedup vs baseline: 1.4017x; 1.4017x over previous
#include <cuda_runtime.h>
#include <cuda_fp16.h>
#include <cstdint>

typedef unsigned long long ull;

#define CDIM 256
#define KCB  8192
#define NTOK 16384
#define OUT_ELEMS (16*256*32*32)
#define MARGIN 6e-4f

#define KSPL 8                               // codebook splits
#define NCH  (128 / KSPL)                    // 64-code chunks per CTA
#define VQ_SMEM (65536 + 2*32768)            // tokens + 2 code stages
#define RR_SMEM (65536 + 32768 + 512)        // codes + 32 tokens + red

__device__ float   g_en[KCB * CDIM];         // normalized codebook fp32
__device__ float   g_corr[KCB];              // 0.5*|e_n|^2
__device__ __half2 g_e2[KCB * 128];          // half2 codebook, [k/64][c2][k%64]
__device__ float   g_zf[NTOK * CDIM];        // normalized tokens fp32 row-major
__device__ __half2 g_z2[NTOK * 128];         // half2 tokens, [n/128][c2][n%128]
__device__ ull     g_topP[KSPL * NTOK];      // per-split packed (score|invidx)
__device__ float   g_top2[KSPL * NTOK];      // per-split second-best
__device__ int     g_idx[NTOK];
__device__ int     g_nflag;
__device__ int     g_list[NTOK];
__device__ ull     g_bestm[NTOK];

// ---------------- helpers ----------------
__device__ __forceinline__ uint32_t smem_u32(const void* p) {
    uint32_t a;
    asm("{ .reg .u64 t; cvta.to.shared.u64 t, %1; cvt.u32.u64 %0, t; }" : "=r"(a) : "l"(p));
    return a;
}
#define CP16(dst, src) asm volatile("cp.async.cg.shared.global [%0], [%1], 16;" :: "r"(dst), "l"(src) : "memory")
#define CP_COMMIT()    asm volatile("cp.async.commit_group;" ::: "memory")
#define CP_WAIT1()     asm volatile("cp.async.wait_group 1;" ::: "memory")
#define CP_WAIT0()     asm volatile("cp.async.wait_group 0;" ::: "memory")

__device__ __forceinline__ unsigned fmap(float v) {
    unsigned u = __float_as_uint(v);
    return (u & 0x80000000u) ? ~u : (u | 0x80000000u);
}
__device__ __forceinline__ float funmap(unsigned u) {
    return __uint_as_float((u & 0x80000000u) ? (u ^ 0x80000000u) : ~u);
}

// ---------------- preprocessing ----------------
__global__ void norm_codebook(const float* __restrict__ emb) {
    if (blockIdx.x == 0 && threadIdx.x == 0) g_nflag = 0;
    int row  = blockIdx.x * 8 + (threadIdx.x >> 5);
    int lane = threadIdx.x & 31;
    const float4* w = (const float4*)(emb + (size_t)row * CDIM);
    float4 a = __ldg(w + lane);
    float4 b = __ldg(w + lane + 32);
    float ss = a.x*a.x + a.y*a.y + a.z*a.z + a.w*a.w
             + b.x*b.x + b.y*b.y + b.z*b.z + b.w*b.w;
    #pragma unroll
    for (int s = 16; s; s >>= 1) ss += __shfl_xor_sync(0xffffffffu, ss, s);
    float inv = 1.0f / fmaxf(sqrtf(ss), 1e-12f);
    float v[8];
    v[0]=a.x*inv; v[1]=a.y*inv; v[2]=a.z*inv; v[3]=a.w*inv;
    v[4]=b.x*inv; v[5]=b.y*inv; v[6]=b.z*inv; v[7]=b.w*inv;
    float4* o = (float4*)(g_en + (size_t)row * CDIM);
    o[lane]      = make_float4(v[0], v[1], v[2], v[3]);
    o[lane + 32] = make_float4(v[4], v[5], v[6], v[7]);
    size_t base = (size_t)(row >> 6) * 8192 + (row & 63);
    g_e2[base + (size_t)(2*lane    ) * 64] = __floats2half2_rn(v[0], v[1]);
    g_e2[base + (size_t)(2*lane + 1) * 64] = __floats2half2_rn(v[2], v[3]);
    g_e2[base + (size_t)(64 + 2*lane    ) * 64] = __floats2half2_rn(v[4], v[5]);
    g_e2[base + (size_t)(64 + 2*lane + 1) * 64] = __floats2half2_rn(v[6], v[7]);
    float ss2 = 0.f;
    #pragma unroll
    for (int j = 0; j < 8; j++) ss2 = fmaf(v[j], v[j], ss2);
    #pragma unroll
    for (int s = 16; s; s >>= 1) ss2 += __shfl_xor_sync(0xffffffffu, ss2, s);
    if (lane == 0) g_corr[row] = 0.5f * ss2;
}

__global__ void __launch_bounds__(256) norm_tokens(const float* __restrict__ z) {
    __shared__ float ssh[2][128];
    int n0 = blockIdx.x * 128;
    int b   = n0 >> 10;
    int hw0 = n0 & 1023;
    int tt = threadIdx.x & 127;
    int p  = threadIdx.x >> 7;
    const float* zp = z + ((size_t)b * CDIM + p * 128) * 1024 + hw0 + tt;

    float ss = 0.f;
    #pragma unroll 8
    for (int c = 0; c < 128; c++) { float v = zp[(size_t)c * 1024]; ss = fmaf(v, v, ss); }
    ssh[p][tt] = ss;
    __syncthreads();
    float inv = 1.0f / fmaxf(sqrtf(ssh[0][tt] + ssh[1][tt]), 1e-12f);

    int n = n0 + tt;
    float* zfout = g_zf + (size_t)n * CDIM + p * 128;
    __half2* z2out = g_z2 + (size_t)blockIdx.x * 16384 + tt;
    #pragma unroll 2
    for (int c = 0; c < 128; c += 8) {
        float v[8];
        #pragma unroll
        for (int j = 0; j < 8; j++) v[j] = zp[(size_t)(c + j) * 1024] * inv;
        *(float4*)(zfout + c)     = make_float4(v[0], v[1], v[2], v[3]);
        *(float4*)(zfout + c + 4) = make_float4(v[4], v[5], v[6], v[7]);
        #pragma unroll
        for (int q = 0; q < 4; q++) {
            int c2 = p * 64 + (c >> 1) + q;
            z2out[(size_t)c2 * 128] = __floats2half2_rn(v[2*q], v[2*q+1]);
        }
    }
}

// ---------------- main: HFMA2 partial GEMM (K-split), per-split top-2 ----------------
__global__ void __launch_bounds__(256, 1) vq_main() {
    extern __shared__ __align__(16) char smem[];
    __half2* tokS = (__half2*)smem;                       // [128 c2][128 tok]
    const uint32_t sa = smem_u32(smem);
    const int tid = threadIdx.x, tc = tid & 15, tg = tid >> 4;
    const int kspl = blockIdx.x >> 7;                     // ksplit-major for L2 reuse
    const int tile = blockIdx.x & 127;
    const int n0 = tile * 128;
    const int gc0 = kspl * NCH;

    {
        const __half2* zsrc = g_z2 + (size_t)tile * 16384;
        #pragma unroll
        for (int j = 0; j < 16; j++) { int i = tid + j*256; CP16(sa + i*16, zsrc + i*4); }
        const __half2* e0 = g_e2 + (size_t)gc0 * 8192;
        #pragma unroll
        for (int j = 0; j < 8; j++)  { int i = tid + j*256; CP16(sa + 65536 + i*16, e0 + i*4); }
        CP_COMMIT();
        #pragma unroll
        for (int j = 0; j < 8; j++)  { int i = tid + j*256; CP16(sa + 65536 + 32768 + i*16, e0 + 8192 + i*4); }
        CP_COMMIT();
    }

    float v1[8], v2[8]; int i1[8];
    #pragma unroll
    for (int t = 0; t < 8; t++) { v1[t] = -1e30f; v2[t] = -1e30f; i1[t] = 0; }

    for (int ch = 0; ch < NCH; ch++) {
        if (ch == NCH - 1) CP_WAIT0(); else CP_WAIT1();
        __syncthreads();

        const __half2* codeS = (const __half2*)(smem + 65536 + (ch & 1) * 32768);
        float facc[8][4];
        #pragma unroll
        for (int t = 0; t < 8; t++)
            #pragma unroll
            for (int j = 0; j < 4; j++) facc[t][j] = 0.f;

        #pragma unroll
        for (int seg = 0; seg < 4; seg++) {
            __half2 acc2[2][8][4];                       // parity-split chains
            const __half2 hz = __float2half2_rn(0.f);
            #pragma unroll
            for (int pp = 0; pp < 2; pp++)
                #pragma unroll
                for (int t = 0; t < 8; t++)
                    #pragma unroll
                    for (int j = 0; j < 4; j++) acc2[pp][t][j] = hz;

            #pragma unroll 4
            for (int cs = 0; cs < 32; cs++) {
                int c2 = seg * 32 + cs;
                int pp = cs & 1;
                __half2 zv[8], ev[4];
                *(uint4*)&zv[0] = *(const uint4*)(tokS + c2*128 + tg*8);
                *(uint4*)&zv[4] = *(const uint4*)(tokS + c2*128 + tg*8 + 4);
                *(uint4*)&ev[0] = *(const uint4*)(codeS + c2*64 + tc*4);
                #pragma unroll
                for (int t = 0; t < 8; t++)
                    #pragma unroll
                    for (int j = 0; j < 4; j++)
                        acc2[pp][t][j] = __hfma2(zv[t], ev[j], acc2[pp][t][j]);
            }
            // HADD2-combined flush: merge parity chains in fp16, convert once
            #pragma unroll
            for (int t = 0; t < 8; t++)
                #pragma unroll
                for (int j = 0; j < 4; j++) {
                    __half2 sum = __hadd2(acc2[0][t][j], acc2[1][t][j]);
                    facc[t][j] += __low2float(sum) + __high2float(sum);
                }
        }
        __syncthreads();

        if (ch + 2 < NCH) {
            const __half2* esrc = g_e2 + (size_t)(gc0 + ch + 2) * 8192;
            uint32_t db = sa + 65536 + (ch & 1) * 32768;
            #pragma unroll
            for (int j = 0; j < 8; j++) { int i = tid + j*256; CP16(db + i*16, esrc + i*4); }
        }
        CP_COMMIT();

        int kbase = (gc0 + ch) * 64 + tc * 4;
        #pragma unroll
        for (int t = 0; t < 8; t++)
            #pragma unroll
            for (int j = 0; j < 4; j++) {
                float s = facc[t][j];
                if (s > v1[t]) { v2[t] = v1[t]; v1[t] = s; i1[t] = kbase + j; }
                else if (s > v2[t]) v2[t] = s;
            }
    }

    #pragma unroll
    for (int t = 0; t < 8; t++) {
        ull p = ((ull)fmap(v1[t]) << 13) | (ull)(8191 - i1[t]);
        float s2 = v2[t];
        #pragma unroll
        for (int x = 1; x <= 8; x <<= 1) {
            ull po = __shfl_xor_sync(0xffffffffu, p, x);
            float s2o = __shfl_xor_sync(0xffffffffu, s2, x);
            float va = funmap((unsigned)(p >> 13));
            float vb = funmap((unsigned)(po >> 13));
            s2 = fmaxf(fmaxf(s2, s2o), fminf(va, vb));
            if (po > p) p = po;
        }
        if (tc == 0) {
            int n = n0 + tg * 8 + t;
            g_topP[kspl * NTOK + n] = p;
            g_top2[kspl * NTOK + n] = s2;
        }
    }
}

// ---------------- merge K-split partials, compute margin, build list ----------------
__global__ void merge_tok() {
    int n = blockIdx.x * 256 + threadIdx.x;
    ull best = g_topP[n];
    float v1 = funmap((unsigned)(best >> 13));
    float v2 = g_top2[n];
    #pragma unroll
    for (int s = 1; s < KSPL; s++) {
        ull p = g_topP[s * NTOK + n];
        float w1 = funmap((unsigned)(p >> 13));
        float w2 = g_top2[s * NTOK + n];
        v2 = fmaxf(fmaxf(v2, w2), fminf(v1, w1));
        if (p > best) { best = p; v1 = w1; }
    }
    g_idx[n] = 8191 - (int)(best & 0x1FFF);
    if (v1 - v2 < MARGIN) {
        g_bestm[n] = 0ull;
        int pos = atomicAdd(&g_nflag, 1);
        g_list[pos] = n;
    }
}

// ---------------- rerank: 128 blocks x 64 codes, 32 tokens/iter, 8 tok/thread ----------------
__global__ void __launch_bounds__(256, 1) rerank_part() {
    int cnt = *(volatile int*)&g_nflag;
    if (cnt == 0) return;

    extern __shared__ __align__(16) char rsm[];
    float4* ecv = (float4*)rsm;                 // [64 c4][64 code]
    float4* tzv = (float4*)(rsm + 65536);       // [32 tok][64 c4]
    ull*    red = (ull*)(rsm + 65536 + 32768);  // [32 tok][2 w]

    const int tid = threadIdx.x;
    const int cl  = tid & 63;
    const int g   = tid >> 6;
    const int k0  = blockIdx.x * 64;
    const int k   = k0 + cl;
    const float corr = __ldg(&g_corr[k]);

    {
        const float4* src = (const float4*)(g_en + (size_t)k * CDIM) + g * 16;
        #pragma unroll
        for (int j = 0; j < 16; j++) {
            float4 vv = __ldg(src + j);
            ecv[(g * 16 + j) * 64 + cl] = vv;
        }
    }
    __syncthreads();

    const int witer = (cnt + 31) >> 5;
    for (int it = 0; it < witer; it++) {
        #pragma unroll
        for (int j = 0; j < 8; j++) {
            int i = tid + j * 256;
            int tok = i >> 6, c4 = i & 63;
            int li = it * 32 + tok;
            int n = g_list[(li < cnt) ? li : 0];
            tzv[tok * 64 + c4] = __ldg((const float4*)(g_zf + (size_t)n * CDIM) + c4);
        }
        __syncthreads();

        float s[8];
        #pragma unroll
        for (int t = 0; t < 8; t++) s[t] = 0.f;
        const float4* tz0 = tzv + (g * 8) * 64;
        #pragma unroll 4
        for (int c4 = 0; c4 < 64; c4++) {
            float4 ev = ecv[c4 * 64 + cl];
            #pragma unroll
            for (int t = 0; t < 8; t++) {
                float4 zz = tz0[t * 64 + c4];
                s[t] = fmaf(zz.x, ev.x, s[t]);
                s[t] = fmaf(zz.y, ev.y, s[t]);
                s[t] = fmaf(zz.z, ev.z, s[t]);
                s[t] = fmaf(zz.w, ev.w, s[t]);
            }
        }
        __syncthreads();

        #pragma unroll
        for (int t = 0; t < 8; t++) {
            ull p = ((ull)fmap(s[t] - corr) << 13) | (ull)(8191 - k);
            #pragma unroll
            for (int x = 16; x; x >>= 1) {
                ull o = __shfl_xor_sync(0xffffffffu, p, x);
                if (o > p) p = o;
            }
            if ((tid & 31) == 0) red[(g * 8 + t) * 2 + ((tid >> 5) & 1)] = p;
        }
        __syncthreads();
        if (tid < 32) {
            int li = it * 32 + tid;
            if (li < cnt) {
                ull a = red[tid * 2], b = red[tid * 2 + 1];
                ull p = (b > a) ? b : a;
                atomicMax(&g_bestm[g_list[li]], p);
            }
        }
        __syncthreads();
    }
}

__global__ void rerank_fix() {
    int i = blockIdx.x * 256 + threadIdx.x;
    if (i < *(volatile int*)&g_nflag) {
        int n = g_list[i];
        g_idx[n] = 8191 - (int)(g_bestm[n] & 0x1FFF);
    }
}

// ---------------- output ----------------
__global__ void __launch_bounds__(256) gather_out(float* __restrict__ out) {
    __shared__ float s[32][CDIM + 1];
    __shared__ int sidx[32];
    int n0 = blockIdx.x * 32;
    if (threadIdx.x < 32) sidx[threadIdx.x] = g_idx[n0 + threadIdx.x];
    __syncthreads();
    #pragma unroll 4
    for (int i = 0; i < 32; i++) {
        int lin = threadIdx.x + i * 256;
        int t = lin >> 8, c = lin & 255;
        s[t][c] = g_en[(size_t)sidx[t] * CDIM + c];
    }
    __syncthreads();
    int b   = n0 >> 10;
    int hw0 = n0 & 1023;
    #pragma unroll 4
    for (int i = 0; i < 32; i++) {
        int lin = threadIdx.x + i * 256;
        int c = lin >> 5, t = lin & 31;
        out[((size_t)b * CDIM + c) * 1024 + hw0 + t] = s[t][c];
    }
}

__global__ void idx_out(float* __restrict__ o) {
    int n = blockIdx.x * 256 + threadIdx.x;
    o[n] = (float)g_idx[n];
}

extern "C" void kernel_launch(void* const* d_in, const int* in_sizes, int n_in,
                              void* d_out, int out_size) {
    const float* z   = (const float*)d_in[0];
    const float* emb = (const float*)d_in[1];
    float* out = (float*)d_out;

    cudaFuncSetAttribute(vq_main,     cudaFuncAttributeMaxDynamicSharedMemorySize, VQ_SMEM);
    cudaFuncSetAttribute(rerank_part, cudaFuncAttributeMaxDynamicSharedMemorySize, RR_SMEM);

    norm_codebook<<<KCB / 8, 256>>>(emb);
    norm_tokens<<<NTOK / 128, 256>>>(z);
    vq_main<<<128 * KSPL, 256, VQ_SMEM>>>();
    merge_tok<<<NTOK / 256, 256>>>();
    rerank_part<<<128, 256, RR_SMEM>>>();
    rerank_fix<<<NTOK / 256, 256>>>();
    gather_out<<<NTOK / 32, 256>>>(out);
    if (out_size >= OUT_ELEMS + NTOK)
        idx_out<<<NTOK / 256, 256>>>(out + OUT_ELEMS);
}

// round 16
// speedup vs baseline: 1.4379x; 1.0258x over previous
#include <cuda_runtime.h>
#include <cuda_fp16.h>
#include <cstdint>

typedef unsigned long long ull;

#define CDIM 256
#define KCB  8192
#define NTOK 16384
#define OUT_ELEMS (16*256*32*32)
#define MARGIN 6e-4f

#define KSPL 8                               // codebook splits
#define NCH  (128 / KSPL)                    // 64-code chunks per CTA
#define VQ_SMEM (65536 + 3*32768)            // tokens + 3 code stages (160 KB)
#define RR_SMEM (65536 + 32768 + 512)        // codes + 32 tokens + red

__device__ float   g_en[KCB * CDIM];         // normalized codebook fp32
__device__ float   g_corr[KCB];              // 0.5*|e_n|^2
__device__ __half2 g_e2[KCB * 128];          // half2 codebook, [k/64][c2][k%64]
__device__ float   g_zf[NTOK * CDIM];        // normalized tokens fp32 row-major
__device__ __half2 g_z2[NTOK * 128];         // half2 tokens, [n/128][c2][n%128]
__device__ ull     g_topP[KSPL * NTOK];      // per-split packed (score|invidx)
__device__ float   g_top2[KSPL * NTOK];      // per-split second-best
__device__ int     g_idx[NTOK];
__device__ int     g_nflag;
__device__ int     g_list[NTOK];
__device__ ull     g_bestm[NTOK];

// ---------------- helpers ----------------
__device__ __forceinline__ uint32_t smem_u32(const void* p) {
    uint32_t a;
    asm("{ .reg .u64 t; cvta.to.shared.u64 t, %1; cvt.u32.u64 %0, t; }" : "=r"(a) : "l"(p));
    return a;
}
#define CP16(dst, src) asm volatile("cp.async.cg.shared.global [%0], [%1], 16;" :: "r"(dst), "l"(src) : "memory")
#define CP_COMMIT()    asm volatile("cp.async.commit_group;" ::: "memory")
#define CP_WAIT1()     asm volatile("cp.async.wait_group 1;" ::: "memory")
#define CP_WAIT0()     asm volatile("cp.async.wait_group 0;" ::: "memory")

__device__ __forceinline__ unsigned fmap(float v) {
    unsigned u = __float_as_uint(v);
    return (u & 0x80000000u) ? ~u : (u | 0x80000000u);
}
__device__ __forceinline__ float funmap(unsigned u) {
    return __uint_as_float((u & 0x80000000u) ? (u ^ 0x80000000u) : ~u);
}

// ---------------- preprocessing ----------------
__global__ void norm_codebook(const float* __restrict__ emb) {
    if (blockIdx.x == 0 && threadIdx.x == 0) g_nflag = 0;
    int row  = blockIdx.x * 8 + (threadIdx.x >> 5);
    int lane = threadIdx.x & 31;
    const float4* w = (const float4*)(emb + (size_t)row * CDIM);
    float4 a = __ldg(w + lane);
    float4 b = __ldg(w + lane + 32);
    float ss = a.x*a.x + a.y*a.y + a.z*a.z + a.w*a.w
             + b.x*b.x + b.y*b.y + b.z*b.z + b.w*b.w;
    #pragma unroll
    for (int s = 16; s; s >>= 1) ss += __shfl_xor_sync(0xffffffffu, ss, s);
    float inv = 1.0f / fmaxf(sqrtf(ss), 1e-12f);
    float v[8];
    v[0]=a.x*inv; v[1]=a.y*inv; v[2]=a.z*inv; v[3]=a.w*inv;
    v[4]=b.x*inv; v[5]=b.y*inv; v[6]=b.z*inv; v[7]=b.w*inv;
    float4* o = (float4*)(g_en + (size_t)row * CDIM);
    o[lane]      = make_float4(v[0], v[1], v[2], v[3]);
    o[lane + 32] = make_float4(v[4], v[5], v[6], v[7]);
    size_t base = (size_t)(row >> 6) * 8192 + (row & 63);
    g_e2[base + (size_t)(2*lane    ) * 64] = __floats2half2_rn(v[0], v[1]);
    g_e2[base + (size_t)(2*lane + 1) * 64] = __floats2half2_rn(v[2], v[3]);
    g_e2[base + (size_t)(64 + 2*lane    ) * 64] = __floats2half2_rn(v[4], v[5]);
    g_e2[base + (size_t)(64 + 2*lane + 1) * 64] = __floats2half2_rn(v[6], v[7]);
    float ss2 = 0.f;
    #pragma unroll
    for (int j = 0; j < 8; j++) ss2 = fmaf(v[j], v[j], ss2);
    #pragma unroll
    for (int s = 16; s; s >>= 1) ss2 += __shfl_xor_sync(0xffffffffu, ss2, s);
    if (lane == 0) g_corr[row] = 0.5f * ss2;
}

__global__ void __launch_bounds__(256) norm_tokens(const float* __restrict__ z) {
    __shared__ float ssh[2][128];
    int n0 = blockIdx.x * 128;
    int b   = n0 >> 10;
    int hw0 = n0 & 1023;
    int tt = threadIdx.x & 127;
    int p  = threadIdx.x >> 7;
    const float* zp = z + ((size_t)b * CDIM + p * 128) * 1024 + hw0 + tt;

    float ss = 0.f;
    #pragma unroll 8
    for (int c = 0; c < 128; c++) { float v = zp[(size_t)c * 1024]; ss = fmaf(v, v, ss); }
    ssh[p][tt] = ss;
    __syncthreads();
    float inv = 1.0f / fmaxf(sqrtf(ssh[0][tt] + ssh[1][tt]), 1e-12f);

    int n = n0 + tt;
    float* zfout = g_zf + (size_t)n * CDIM + p * 128;
    __half2* z2out = g_z2 + (size_t)blockIdx.x * 16384 + tt;
    #pragma unroll 2
    for (int c = 0; c < 128; c += 8) {
        float v[8];
        #pragma unroll
        for (int j = 0; j < 8; j++) v[j] = zp[(size_t)(c + j) * 1024] * inv;
        *(float4*)(zfout + c)     = make_float4(v[0], v[1], v[2], v[3]);
        *(float4*)(zfout + c + 4) = make_float4(v[4], v[5], v[6], v[7]);
        #pragma unroll
        for (int q = 0; q < 4; q++) {
            int c2 = p * 64 + (c >> 1) + q;
            z2out[(size_t)c2 * 128] = __floats2half2_rn(v[2*q], v[2*q+1]);
        }
    }
}

// ---------------- main: HFMA2 partial GEMM, 3-stage ring, one barrier/chunk ----------------
__global__ void __launch_bounds__(256, 1) vq_main() {
    extern __shared__ __align__(16) char smem[];
    __half2* tokS = (__half2*)smem;                       // [128 c2][128 tok]
    const uint32_t sa = smem_u32(smem);
    const int tid = threadIdx.x, tc = tid & 15, tg = tid >> 4;
    const int kspl = blockIdx.x >> 7;                     // ksplit-major for L2 reuse
    const int tile = blockIdx.x & 127;
    const int n0 = tile * 128;
    const int gc0 = kspl * NCH;

    // prologue: tokens + stages 0,1
    {
        const __half2* zsrc = g_z2 + (size_t)tile * 16384;
        #pragma unroll
        for (int j = 0; j < 16; j++) { int i = tid + j*256; CP16(sa + i*16, zsrc + i*4); }
        const __half2* e0 = g_e2 + (size_t)gc0 * 8192;
        #pragma unroll
        for (int j = 0; j < 8; j++)  { int i = tid + j*256; CP16(sa + 65536 + i*16, e0 + i*4); }
        CP_COMMIT();
        #pragma unroll
        for (int j = 0; j < 8; j++)  { int i = tid + j*256; CP16(sa + 65536 + 32768 + i*16, e0 + 8192 + i*4); }
        CP_COMMIT();
    }

    float v1[8], v2[8]; int i1[8];
    #pragma unroll
    for (int t = 0; t < 8; t++) { v1[t] = -1e30f; v2[t] = -1e30f; i1[t] = 0; }

    int st = 0;                                           // ch % 3
    for (int ch = 0; ch < NCH; ch++) {
        CP_WAIT1();
        __syncthreads();                                  // stage st ready; all warps done ch-1

        // prefetch ch+2 into stage (st+2)%3 — safe: consumed at ch-1
        {
            int st2 = st + 2; if (st2 >= 3) st2 -= 3;
            if (ch + 2 < NCH) {
                const __half2* esrc = g_e2 + (size_t)(gc0 + ch + 2) * 8192;
                uint32_t db = sa + 65536 + st2 * 32768;
                #pragma unroll
                for (int j = 0; j < 8; j++) { int i = tid + j*256; CP16(db + i*16, esrc + i*4); }
            }
            CP_COMMIT();                                  // uniform accounting
        }

        const __half2* codeS = (const __half2*)(smem + 65536 + st * 32768);
        float facc[8][4];
        #pragma unroll
        for (int t = 0; t < 8; t++)
            #pragma unroll
            for (int j = 0; j < 4; j++) facc[t][j] = 0.f;

        #pragma unroll
        for (int seg = 0; seg < 4; seg++) {
            __half2 acc2[2][8][4];                       // parity-split chains
            const __half2 hz = __float2half2_rn(0.f);
            #pragma unroll
            for (int pp = 0; pp < 2; pp++)
                #pragma unroll
                for (int t = 0; t < 8; t++)
                    #pragma unroll
                    for (int j = 0; j < 4; j++) acc2[pp][t][j] = hz;

            #pragma unroll 4
            for (int cs = 0; cs < 32; cs++) {
                int c2 = seg * 32 + cs;
                int pp = cs & 1;
                __half2 zv[8], ev[4];
                *(uint4*)&zv[0] = *(const uint4*)(tokS + c2*128 + tg*8);
                *(uint4*)&zv[4] = *(const uint4*)(tokS + c2*128 + tg*8 + 4);
                *(uint4*)&ev[0] = *(const uint4*)(codeS + c2*64 + tc*4);
                #pragma unroll
                for (int t = 0; t < 8; t++)
                    #pragma unroll
                    for (int j = 0; j < 4; j++)
                        acc2[pp][t][j] = __hfma2(zv[t], ev[j], acc2[pp][t][j]);
            }
            #pragma unroll
            for (int t = 0; t < 8; t++)
                #pragma unroll
                for (int j = 0; j < 4; j++)
                    facc[t][j] += (__low2float(acc2[0][t][j]) + __high2float(acc2[0][t][j]))
                                + (__low2float(acc2[1][t][j]) + __high2float(acc2[1][t][j]));
        }

        int kbase = (gc0 + ch) * 64 + tc * 4;
        #pragma unroll
        for (int t = 0; t < 8; t++)
            #pragma unroll
            for (int j = 0; j < 4; j++) {
                float s = facc[t][j];
                if (s > v1[t]) { v2[t] = v1[t]; v1[t] = s; i1[t] = kbase + j; }
                else if (s > v2[t]) v2[t] = s;
            }

        if (++st >= 3) st -= 3;
    }

    #pragma unroll
    for (int t = 0; t < 8; t++) {
        ull p = ((ull)fmap(v1[t]) << 13) | (ull)(8191 - i1[t]);
        float s2 = v2[t];
        #pragma unroll
        for (int x = 1; x <= 8; x <<= 1) {
            ull po = __shfl_xor_sync(0xffffffffu, p, x);
            float s2o = __shfl_xor_sync(0xffffffffu, s2, x);
            float va = funmap((unsigned)(p >> 13));
            float vb = funmap((unsigned)(po >> 13));
            s2 = fmaxf(fmaxf(s2, s2o), fminf(va, vb));
            if (po > p) p = po;
        }
        if (tc == 0) {
            int n = n0 + tg * 8 + t;
            g_topP[kspl * NTOK + n] = p;
            g_top2[kspl * NTOK + n] = s2;
        }
    }
}

// ---------------- merge K-split partials, compute margin, build list ----------------
__global__ void merge_tok() {
    int n = blockIdx.x * 256 + threadIdx.x;
    ull best = g_topP[n];
    float v1 = funmap((unsigned)(best >> 13));
    float v2 = g_top2[n];
    #pragma unroll
    for (int s = 1; s < KSPL; s++) {
        ull p = g_topP[s * NTOK + n];
        float w1 = funmap((unsigned)(p >> 13));
        float w2 = g_top2[s * NTOK + n];
        v2 = fmaxf(fmaxf(v2, w2), fminf(v1, w1));
        if (p > best) { best = p; v1 = w1; }
    }
    g_idx[n] = 8191 - (int)(best & 0x1FFF);
    if (v1 - v2 < MARGIN) {
        g_bestm[n] = 0ull;
        int pos = atomicAdd(&g_nflag, 1);
        g_list[pos] = n;
    }
}

// ---------------- rerank: 128 blocks x 64 codes, 32 tokens/iter, 8 tok/thread ----------------
__global__ void __launch_bounds__(256, 1) rerank_part() {
    int cnt = *(volatile int*)&g_nflag;
    if (cnt == 0) return;

    extern __shared__ __align__(16) char rsm[];
    float4* ecv = (float4*)rsm;                 // [64 c4][64 code]
    float4* tzv = (float4*)(rsm + 65536);       // [32 tok][64 c4]
    ull*    red = (ull*)(rsm + 65536 + 32768);  // [32 tok][2 w]

    const int tid = threadIdx.x;
    const int cl  = tid & 63;
    const int g   = tid >> 6;
    const int k0  = blockIdx.x * 64;
    const int k   = k0 + cl;
    const float corr = __ldg(&g_corr[k]);

    {
        const float4* src = (const float4*)(g_en + (size_t)k * CDIM) + g * 16;
        #pragma unroll
        for (int j = 0; j < 16; j++) {
            float4 vv = __ldg(src + j);
            ecv[(g * 16 + j) * 64 + cl] = vv;
        }
    }
    __syncthreads();

    const int witer = (cnt + 31) >> 5;
    for (int it = 0; it < witer; it++) {
        #pragma unroll
        for (int j = 0; j < 8; j++) {
            int i = tid + j * 256;
            int tok = i >> 6, c4 = i & 63;
            int li = it * 32 + tok;
            int n = g_list[(li < cnt) ? li : 0];
            tzv[tok * 64 + c4] = __ldg((const float4*)(g_zf + (size_t)n * CDIM) + c4);
        }
        __syncthreads();

        float s[8];
        #pragma unroll
        for (int t = 0; t < 8; t++) s[t] = 0.f;
        const float4* tz0 = tzv + (g * 8) * 64;
        #pragma unroll 4
        for (int c4 = 0; c4 < 64; c4++) {
            float4 ev = ecv[c4 * 64 + cl];
            #pragma unroll
            for (int t = 0; t < 8; t++) {
                float4 zz = tz0[t * 64 + c4];
                s[t] = fmaf(zz.x, ev.x, s[t]);
                s[t] = fmaf(zz.y, ev.y, s[t]);
                s[t] = fmaf(zz.z, ev.z, s[t]);
                s[t] = fmaf(zz.w, ev.w, s[t]);
            }
        }
        __syncthreads();

        #pragma unroll
        for (int t = 0; t < 8; t++) {
            ull p = ((ull)fmap(s[t] - corr) << 13) | (ull)(8191 - k);
            #pragma unroll
            for (int x = 16; x; x >>= 1) {
                ull o = __shfl_xor_sync(0xffffffffu, p, x);
                if (o > p) p = o;
            }
            if ((tid & 31) == 0) red[(g * 8 + t) * 2 + ((tid >> 5) & 1)] = p;
        }
        __syncthreads();
        if (tid < 32) {
            int li = it * 32 + tid;
            if (li < cnt) {
                ull a = red[tid * 2], b = red[tid * 2 + 1];
                ull p = (b > a) ? b : a;
                atomicMax(&g_bestm[g_list[li]], p);
            }
        }
        __syncthreads();
    }
}

__global__ void rerank_fix() {
    int i = blockIdx.x * 256 + threadIdx.x;
    if (i < *(volatile int*)&g_nflag) {
        int n = g_list[i];
        g_idx[n] = 8191 - (int)(g_bestm[n] & 0x1FFF);
    }
}

// ---------------- output ----------------
__global__ void __launch_bounds__(256) gather_out(float* __restrict__ out) {
    __shared__ float s[32][CDIM + 1];
    __shared__ int sidx[32];
    int n0 = blockIdx.x * 32;
    if (threadIdx.x < 32) sidx[threadIdx.x] = g_idx[n0 + threadIdx.x];
    __syncthreads();
    #pragma unroll 4
    for (int i = 0; i < 32; i++) {
        int lin = threadIdx.x + i * 256;
        int t = lin >> 8, c = lin & 255;
        s[t][c] = g_en[(size_t)sidx[t] * CDIM + c];
    }
    __syncthreads();
    int b   = n0 >> 10;
    int hw0 = n0 & 1023;
    #pragma unroll 4
    for (int i = 0; i < 32; i++) {
        int lin = threadIdx.x + i * 256;
        int c = lin >> 5, t = lin & 31;
        out[((size_t)b * CDIM + c) * 1024 + hw0 + t] = s[t][c];
    }
}

__global__ void idx_out(float* __restrict__ o) {
    int n = blockIdx.x * 256 + threadIdx.x;
    o[n] = (float)g_idx[n];
}

extern "C" void kernel_launch(void* const* d_in, const int* in_sizes, int n_in,
                              void* d_out, int out_size) {
    const float* z   = (const float*)d_in[0];
    const float* emb = (const float*)d_in[1];
    float* out = (float*)d_out;

    cudaFuncSetAttribute(vq_main,     cudaFuncAttributeMaxDynamicSharedMemorySize, VQ_SMEM);
    cudaFuncSetAttribute(rerank_part, cudaFuncAttributeMaxDynamicSharedMemorySize, RR_SMEM);

    norm_codebook<<<KCB / 8, 256>>>(emb);
    norm_tokens<<<NTOK / 128, 256>>>(z);
    vq_main<<<128 * KSPL, 256, VQ_SMEM>>>();
    merge_tok<<<NTOK / 256, 256>>>();
    rerank_part<<<128, 256, RR_SMEM>>>();
    rerank_fix<<<NTOK / 256, 256>>>();
    gather_out<<<NTOK / 32, 256>>>(out);
    if (out_size >= OUT_ELEMS + NTOK)
        idx_out<<<NTOK / 256, 256>>>(out + OUT_ELEMS);
}

// round 17
// speedup vs baseline: 1.4783x; 1.0281x over previous
#include <cuda_runtime.h>
#include <cuda_fp16.h>
#include <cstdint>

typedef unsigned long long ull;

#define CDIM 256
#define KCB  8192
#define NTOK 16384
#define OUT_ELEMS (16*256*32*32)
#define MARGIN 4e-4f

#define KSPL 8                               // codebook splits
#define NCH  (128 / KSPL)                    // 64-code chunks per CTA
#define VQ_SMEM (65536 + 3*32768)            // tokens + 3 code stages (160 KB)
#define RR_SMEM (65536 + 32768 + 512)        // codes + 32 tokens + red

__device__ float   g_en[KCB * CDIM];         // normalized codebook fp32
__device__ float   g_corr[KCB];              // 0.5*|e_n|^2
__device__ __half2 g_e2[KCB * 128];          // half2 codebook, [k/64][c2][k%64]
__device__ float   g_zf[NTOK * CDIM];        // normalized tokens fp32 row-major
__device__ __half2 g_z2[NTOK * 128];         // half2 tokens, [n/128][c2][n%128]
__device__ ull     g_topP[KSPL * NTOK];      // per-split packed (score|invidx)
__device__ float   g_top2[KSPL * NTOK];      // per-split second-best
__device__ int     g_idx[NTOK];
__device__ int     g_nflag;
__device__ int     g_list[NTOK];
__device__ ull     g_bestm[NTOK];

// ---------------- helpers ----------------
__device__ __forceinline__ uint32_t smem_u32(const void* p) {
    uint32_t a;
    asm("{ .reg .u64 t; cvta.to.shared.u64 t, %1; cvt.u32.u64 %0, t; }" : "=r"(a) : "l"(p));
    return a;
}
#define CP16(dst, src) asm volatile("cp.async.cg.shared.global [%0], [%1], 16;" :: "r"(dst), "l"(src) : "memory")
#define CP_COMMIT()    asm volatile("cp.async.commit_group;" ::: "memory")
#define CP_WAIT1()     asm volatile("cp.async.wait_group 1;" ::: "memory")
#define CP_WAIT0()     asm volatile("cp.async.wait_group 0;" ::: "memory")

__device__ __forceinline__ unsigned fmap(float v) {
    unsigned u = __float_as_uint(v);
    return (u & 0x80000000u) ? ~u : (u | 0x80000000u);
}
__device__ __forceinline__ float funmap(unsigned u) {
    return __uint_as_float((u & 0x80000000u) ? (u ^ 0x80000000u) : ~u);
}

// ---------------- preprocessing ----------------
__global__ void norm_codebook(const float* __restrict__ emb) {
    if (blockIdx.x == 0 && threadIdx.x == 0) g_nflag = 0;
    int row  = blockIdx.x * 8 + (threadIdx.x >> 5);
    int lane = threadIdx.x & 31;
    const float4* w = (const float4*)(emb + (size_t)row * CDIM);
    float4 a = __ldg(w + lane);
    float4 b = __ldg(w + lane + 32);
    float ss = a.x*a.x + a.y*a.y + a.z*a.z + a.w*a.w
             + b.x*b.x + b.y*b.y + b.z*b.z + b.w*b.w;
    #pragma unroll
    for (int s = 16; s; s >>= 1) ss += __shfl_xor_sync(0xffffffffu, ss, s);
    float inv = 1.0f / fmaxf(sqrtf(ss), 1e-12f);
    float v[8];
    v[0]=a.x*inv; v[1]=a.y*inv; v[2]=a.z*inv; v[3]=a.w*inv;
    v[4]=b.x*inv; v[5]=b.y*inv; v[6]=b.z*inv; v[7]=b.w*inv;
    float4* o = (float4*)(g_en + (size_t)row * CDIM);
    o[lane]      = make_float4(v[0], v[1], v[2], v[3]);
    o[lane + 32] = make_float4(v[4], v[5], v[6], v[7]);
    size_t base = (size_t)(row >> 6) * 8192 + (row & 63);
    g_e2[base + (size_t)(2*lane    ) * 64] = __floats2half2_rn(v[0], v[1]);
    g_e2[base + (size_t)(2*lane + 1) * 64] = __floats2half2_rn(v[2], v[3]);
    g_e2[base + (size_t)(64 + 2*lane    ) * 64] = __floats2half2_rn(v[4], v[5]);
    g_e2[base + (size_t)(64 + 2*lane + 1) * 64] = __floats2half2_rn(v[6], v[7]);
    float ss2 = 0.f;
    #pragma unroll
    for (int j = 0; j < 8; j++) ss2 = fmaf(v[j], v[j], ss2);
    #pragma unroll
    for (int s = 16; s; s >>= 1) ss2 += __shfl_xor_sync(0xffffffffu, ss2, s);
    if (lane == 0) g_corr[row] = 0.5f * ss2;
}

__global__ void __launch_bounds__(256) norm_tokens(const float* __restrict__ z) {
    __shared__ float ssh[2][128];
    int n0 = blockIdx.x * 128;
    int b   = n0 >> 10;
    int hw0 = n0 & 1023;
    int tt = threadIdx.x & 127;
    int p  = threadIdx.x >> 7;
    const float* zp = z + ((size_t)b * CDIM + p * 128) * 1024 + hw0 + tt;

    float ss = 0.f;
    #pragma unroll 8
    for (int c = 0; c < 128; c++) { float v = zp[(size_t)c * 1024]; ss = fmaf(v, v, ss); }
    ssh[p][tt] = ss;
    __syncthreads();
    float inv = 1.0f / fmaxf(sqrtf(ssh[0][tt] + ssh[1][tt]), 1e-12f);

    int n = n0 + tt;
    float* zfout = g_zf + (size_t)n * CDIM + p * 128;
    __half2* z2out = g_z2 + (size_t)blockIdx.x * 16384 + tt;
    #pragma unroll 2
    for (int c = 0; c < 128; c += 8) {
        float v[8];
        #pragma unroll
        for (int j = 0; j < 8; j++) v[j] = zp[(size_t)(c + j) * 1024] * inv;
        *(float4*)(zfout + c)     = make_float4(v[0], v[1], v[2], v[3]);
        *(float4*)(zfout + c + 4) = make_float4(v[4], v[5], v[6], v[7]);
        #pragma unroll
        for (int q = 0; q < 4; q++) {
            int c2 = p * 64 + (c >> 1) + q;
            z2out[(size_t)c2 * 128] = __floats2half2_rn(v[2*q], v[2*q+1]);
        }
    }
}

// ---------------- main: HFMA2 partial GEMM, 3-stage ring, one barrier/chunk ----------------
__global__ void __launch_bounds__(256, 1) vq_main() {
    extern __shared__ __align__(16) char smem[];
    __half2* tokS = (__half2*)smem;                       // [128 c2][128 tok]
    const uint32_t sa = smem_u32(smem);
    const int tid = threadIdx.x, tc = tid & 15, tg = tid >> 4;
    const int kspl = blockIdx.x >> 7;                     // ksplit-major for L2 reuse
    const int tile = blockIdx.x & 127;
    const int n0 = tile * 128;
    const int gc0 = kspl * NCH;

    // prologue: tokens + stages 0,1
    {
        const __half2* zsrc = g_z2 + (size_t)tile * 16384;
        #pragma unroll
        for (int j = 0; j < 16; j++) { int i = tid + j*256; CP16(sa + i*16, zsrc + i*4); }
        const __half2* e0 = g_e2 + (size_t)gc0 * 8192;
        #pragma unroll
        for (int j = 0; j < 8; j++)  { int i = tid + j*256; CP16(sa + 65536 + i*16, e0 + i*4); }
        CP_COMMIT();
        #pragma unroll
        for (int j = 0; j < 8; j++)  { int i = tid + j*256; CP16(sa + 65536 + 32768 + i*16, e0 + 8192 + i*4); }
        CP_COMMIT();
    }

    float v1[8], v2[8]; int i1[8];
    #pragma unroll
    for (int t = 0; t < 8; t++) { v1[t] = -1e30f; v2[t] = -1e30f; i1[t] = 0; }

    int st = 0;                                           // ch % 3
    for (int ch = 0; ch < NCH; ch++) {
        CP_WAIT1();
        __syncthreads();                                  // stage st ready; all warps done ch-1

        // prefetch ch+2 into stage (st+2)%3 — safe: consumed at ch-1
        {
            int st2 = st + 2; if (st2 >= 3) st2 -= 3;
            if (ch + 2 < NCH) {
                const __half2* esrc = g_e2 + (size_t)(gc0 + ch + 2) * 8192;
                uint32_t db = sa + 65536 + st2 * 32768;
                #pragma unroll
                for (int j = 0; j < 8; j++) { int i = tid + j*256; CP16(db + i*16, esrc + i*4); }
            }
            CP_COMMIT();                                  // uniform accounting
        }

        const __half2* codeS = (const __half2*)(smem + 65536 + st * 32768);
        float facc[8][4];
        #pragma unroll
        for (int t = 0; t < 8; t++)
            #pragma unroll
            for (int j = 0; j < 4; j++) facc[t][j] = 0.f;

        #pragma unroll
        for (int seg = 0; seg < 4; seg++) {
            __half2 acc2[2][8][4];                       // parity-split chains
            const __half2 hz = __float2half2_rn(0.f);
            #pragma unroll
            for (int pp = 0; pp < 2; pp++)
                #pragma unroll
                for (int t = 0; t < 8; t++)
                    #pragma unroll
                    for (int j = 0; j < 4; j++) acc2[pp][t][j] = hz;

            #pragma unroll 4
            for (int cs = 0; cs < 32; cs++) {
                int c2 = seg * 32 + cs;
                int pp = cs & 1;
                __half2 zv[8], ev[4];
                *(uint4*)&zv[0] = *(const uint4*)(tokS + c2*128 + tg*8);
                *(uint4*)&zv[4] = *(const uint4*)(tokS + c2*128 + tg*8 + 4);
                *(uint4*)&ev[0] = *(const uint4*)(codeS + c2*64 + tc*4);
                #pragma unroll
                for (int t = 0; t < 8; t++)
                    #pragma unroll
                    for (int j = 0; j < 4; j++)
                        acc2[pp][t][j] = __hfma2(zv[t], ev[j], acc2[pp][t][j]);
            }
            #pragma unroll
            for (int t = 0; t < 8; t++)
                #pragma unroll
                for (int j = 0; j < 4; j++)
                    facc[t][j] += (__low2float(acc2[0][t][j]) + __high2float(acc2[0][t][j]))
                                + (__low2float(acc2[1][t][j]) + __high2float(acc2[1][t][j]));
        }

        int kbase = (gc0 + ch) * 64 + tc * 4;
        #pragma unroll
        for (int t = 0; t < 8; t++)
            #pragma unroll
            for (int j = 0; j < 4; j++) {
                float s = facc[t][j];
                if (s > v1[t]) { v2[t] = v1[t]; v1[t] = s; i1[t] = kbase + j; }
                else if (s > v2[t]) v2[t] = s;
            }

        if (++st >= 3) st -= 3;
    }

    #pragma unroll
    for (int t = 0; t < 8; t++) {
        ull p = ((ull)fmap(v1[t]) << 13) | (ull)(8191 - i1[t]);
        float s2 = v2[t];
        #pragma unroll
        for (int x = 1; x <= 8; x <<= 1) {
            ull po = __shfl_xor_sync(0xffffffffu, p, x);
            float s2o = __shfl_xor_sync(0xffffffffu, s2, x);
            float va = funmap((unsigned)(p >> 13));
            float vb = funmap((unsigned)(po >> 13));
            s2 = fmaxf(fmaxf(s2, s2o), fminf(va, vb));
            if (po > p) p = po;
        }
        if (tc == 0) {
            int n = n0 + tg * 8 + t;
            g_topP[kspl * NTOK + n] = p;
            g_top2[kspl * NTOK + n] = s2;
        }
    }
}

// ---------------- merge K-split partials, compute margin, build list ----------------
__global__ void merge_tok() {
    int n = blockIdx.x * 256 + threadIdx.x;
    ull best = g_topP[n];
    float v1 = funmap((unsigned)(best >> 13));
    float v2 = g_top2[n];
    #pragma unroll
    for (int s = 1; s < KSPL; s++) {
        ull p = g_topP[s * NTOK + n];
        float w1 = funmap((unsigned)(p >> 13));
        float w2 = g_top2[s * NTOK + n];
        v2 = fmaxf(fmaxf(v2, w2), fminf(v1, w1));
        if (p > best) { best = p; v1 = w1; }
    }
    g_idx[n] = 8191 - (int)(best & 0x1FFF);
    if (v1 - v2 < MARGIN) {
        g_bestm[n] = 0ull;
        int pos = atomicAdd(&g_nflag, 1);
        g_list[pos] = n;
    }
}

// ---------------- rerank: 128 blocks x 64 codes, 32 tokens/iter, 8 tok/thread ----------------
__global__ void __launch_bounds__(256, 1) rerank_part() {
    int cnt = *(volatile int*)&g_nflag;
    if (cnt == 0) return;

    extern __shared__ __align__(16) char rsm[];
    float4* ecv = (float4*)rsm;                 // [64 c4][64 code]
    float4* tzv = (float4*)(rsm + 65536);       // [32 tok][64 c4]
    ull*    red = (ull*)(rsm + 65536 + 32768);  // [32 tok][2 w]

    const int tid = threadIdx.x;
    const int cl  = tid & 63;
    const int g   = tid >> 6;
    const int k0  = blockIdx.x * 64;
    const int k   = k0 + cl;
    const float corr = __ldg(&g_corr[k]);

    {
        const float4* src = (const float4*)(g_en + (size_t)k * CDIM) + g * 16;
        #pragma unroll
        for (int j = 0; j < 16; j++) {
            float4 vv = __ldg(src + j);
            ecv[(g * 16 + j) * 64 + cl] = vv;
        }
    }
    __syncthreads();

    const int witer = (cnt + 31) >> 5;
    for (int it = 0; it < witer; it++) {
        #pragma unroll
        for (int j = 0; j < 8; j++) {
            int i = tid + j * 256;
            int tok = i >> 6, c4 = i & 63;
            int li = it * 32 + tok;
            int n = g_list[(li < cnt) ? li : 0];
            tzv[tok * 64 + c4] = __ldg((const float4*)(g_zf + (size_t)n * CDIM) + c4);
        }
        __syncthreads();

        float s[8];
        #pragma unroll
        for (int t = 0; t < 8; t++) s[t] = 0.f;
        const float4* tz0 = tzv + (g * 8) * 64;
        #pragma unroll 4
        for (int c4 = 0; c4 < 64; c4++) {
            float4 ev = ecv[c4 * 64 + cl];
            #pragma unroll
            for (int t = 0; t < 8; t++) {
                float4 zz = tz0[t * 64 + c4];
                s[t] = fmaf(zz.x, ev.x, s[t]);
                s[t] = fmaf(zz.y, ev.y, s[t]);
                s[t] = fmaf(zz.z, ev.z, s[t]);
                s[t] = fmaf(zz.w, ev.w, s[t]);
            }
        }
        __syncthreads();

        #pragma unroll
        for (int t = 0; t < 8; t++) {
            ull p = ((ull)fmap(s[t] - corr) << 13) | (ull)(8191 - k);
            #pragma unroll
            for (int x = 16; x; x >>= 1) {
                ull o = __shfl_xor_sync(0xffffffffu, p, x);
                if (o > p) p = o;
            }
            if ((tid & 31) == 0) red[(g * 8 + t) * 2 + ((tid >> 5) & 1)] = p;
        }
        __syncthreads();
        if (tid < 32) {
            int li = it * 32 + tid;
            if (li < cnt) {
                ull a = red[tid * 2], b = red[tid * 2 + 1];
                ull p = (b > a) ? b : a;
                atomicMax(&g_bestm[g_list[li]], p);
            }
        }
        __syncthreads();
    }
}

__global__ void rerank_fix() {
    int i = blockIdx.x * 256 + threadIdx.x;
    if (i < *(volatile int*)&g_nflag) {
        int n = g_list[i];
        g_idx[n] = 8191 - (int)(g_bestm[n] & 0x1FFF);
    }
}

// ---------------- output: gather + transpose; blocks 0-63 also emit index floats ----------------
__global__ void __launch_bounds__(256) gather_out(float* __restrict__ out, int emit_idx) {
    __shared__ float s[32][CDIM + 1];
    __shared__ int sidx[32];
    int n0 = blockIdx.x * 32;
    if (threadIdx.x < 32) sidx[threadIdx.x] = g_idx[n0 + threadIdx.x];
    __syncthreads();
    #pragma unroll 4
    for (int i = 0; i < 32; i++) {
        int lin = threadIdx.x + i * 256;
        int t = lin >> 8, c = lin & 255;
        s[t][c] = g_en[(size_t)sidx[t] * CDIM + c];
    }
    __syncthreads();
    int b   = n0 >> 10;
    int hw0 = n0 & 1023;
    #pragma unroll 4
    for (int i = 0; i < 32; i++) {
        int lin = threadIdx.x + i * 256;
        int c = lin >> 5, t = lin & 31;
        out[((size_t)b * CDIM + c) * 1024 + hw0 + t] = s[t][c];
    }
    if (emit_idx && blockIdx.x < NTOK / 256) {
        int n = blockIdx.x * 256 + threadIdx.x;
        out[OUT_ELEMS + n] = (float)g_idx[n];
    }
}

extern "C" void kernel_launch(void* const* d_in, const int* in_sizes, int n_in,
                              void* d_out, int out_size) {
    const float* z   = (const float*)d_in[0];
    const float* emb = (const float*)d_in[1];
    float* out = (float*)d_out;

    cudaFuncSetAttribute(vq_main,     cudaFuncAttributeMaxDynamicSharedMemorySize, VQ_SMEM);
    cudaFuncSetAttribute(rerank_part, cudaFuncAttributeMaxDynamicSharedMemorySize, RR_SMEM);

    int emit_idx = (out_size >= OUT_ELEMS + NTOK) ? 1 : 0;

    norm_codebook<<<KCB / 8, 256>>>(emb);
    norm_tokens<<<NTOK / 128, 256>>>(z);
    vq_main<<<128 * KSPL, 256, VQ_SMEM>>>();
    merge_tok<<<NTOK / 256, 256>>>();
    rerank_part<<<128, 256, RR_SMEM>>>();
    rerank_fix<<<NTOK / 256, 256>>>();
    gather_out<<<NTOK / 32, 256>>>(out, emit_idx);
}